// round 16
// baseline (speedup 1.0000x reference)
#include <cuda_runtime.h>
#include <cuda_fp16.h>
#include <cstdint>

// ---------------- problem dims ----------------
#define IN_F   4096
#define OUT_F  11008
#define M_TOT  8192
#define GROUPS 32
#define PACKED 512

// ---------------- GEMM tiling ----------------
#define BLOCK_M 128
#define BLOCK_N 128
#define BLOCK_K 64            // 64 halves = 128B rows
#define STAGES  3
#define NITER   (IN_F / BLOCK_K)   // 64
#define NT      (OUT_F / BLOCK_N)  // 86
#define MT      (M_TOT / BLOCK_M)  // 64
#define GROUP_N 16                 // nt-supertile width for L2 locality

#define A_BYTES (BLOCK_M * 128)            // 16384
#define B_BYTES (BLOCK_N * 128)            // 16384
#define STAGE_BYTES (A_BYTES + B_BYTES)    // 32768
#define SMEM_BYTES (STAGES * STAGE_BYTES)  // 98304  (2 CTAs/SM -> 192K)

// prep work split
#define XCHUNKS (M_TOT * IN_F / 8)
#define WWORDS  (OUT_F * PACKED)

// ---------------- scratch (device globals: allocation-free) ----------------
__device__ __align__(1024) __half g_xh[(size_t)M_TOT * IN_F];
__device__ __align__(1024) __half g_wh[(size_t)OUT_F * IN_F];

// ---------------- PTX helpers ----------------
__device__ __forceinline__ uint32_t smem_u32(const void* p) {
    uint32_t a;
    asm("{ .reg .u64 t; cvta.to.shared.u64 t, %1; cvt.u32.u64 %0, t; }" : "=r"(a) : "l"(p));
    return a;
}

#define CP_ASYNC_CG(smem, gptr) \
    asm volatile("cp.async.cg.shared.global [%0], [%1], 16;" :: "r"(smem), "l"(gptr) : "memory")
#define CP_COMMIT() asm volatile("cp.async.commit_group;" ::: "memory")
#define CP_WAIT1()  asm volatile("cp.async.wait_group 1;" ::: "memory")

#define LDSM_X4(R, addr) \
    asm volatile("ldmatrix.sync.aligned.m8n8.x4.shared.b16 {%0,%1,%2,%3}, [%4];" \
                 : "=r"((R)[0]), "=r"((R)[1]), "=r"((R)[2]), "=r"((R)[3]) : "r"(addr))

#define MMA16816(C, A, B) \
    asm volatile("mma.sync.aligned.m16n8k16.row.col.f32.f16.f16.f32 " \
                 "{%0,%1,%2,%3}, {%4,%5,%6,%7}, {%8,%9}, {%0,%1,%2,%3};" \
                 : "+f"((C)[0]), "+f"((C)[1]), "+f"((C)[2]), "+f"((C)[3]) \
                 : "r"((A)[0]), "r"((A)[1]), "r"((A)[2]), "r"((A)[3]), \
                   "r"((B)[0]), "r"((B)[1]))

// streaming (evict-first) fp32x2 store: output is never re-read.
#define STG_CS_F32X2(ptr, vx, vy) \
    asm volatile("st.global.cs.v2.f32 [%0], {%1, %2};" :: "l"(ptr), "f"(vx), "f"(vy) : "memory")

// streaming 16B load (read-once inputs in prep)
__device__ __forceinline__ uint4 ldcs_u4(const uint4* p) {
    uint4 v;
    asm volatile("ld.global.cs.v4.b32 {%0,%1,%2,%3}, [%4];"
                 : "=r"(v.x), "=r"(v.y), "=r"(v.z), "=r"(v.w) : "l"(p));
    return v;
}

// ---------------- kernel 1: fused prep (x fp32->fp16, W int4->fp16) ----------------
__global__ void prep_kernel(const float4* __restrict__ x, uint4* __restrict__ xh,
                            const int* __restrict__ wp, const float* __restrict__ scales,
                            const float* __restrict__ biases, __half* __restrict__ wh) {
    int idx = blockIdx.x * blockDim.x + threadIdx.x;
    if (idx < XCHUNKS) {
        uint4 ua = ldcs_u4((const uint4*)(x + 2 * idx));
        uint4 ub = ldcs_u4((const uint4*)(x + 2 * idx + 1));
        float4 a = *reinterpret_cast<float4*>(&ua);
        float4 b = *reinterpret_cast<float4*>(&ub);
        __half h[8];
        h[0] = __float2half(a.x); h[1] = __float2half(a.y);
        h[2] = __float2half(a.z); h[3] = __float2half(a.w);
        h[4] = __float2half(b.x); h[5] = __float2half(b.y);
        h[6] = __float2half(b.z); h[7] = __float2half(b.w);
        xh[idx] = *reinterpret_cast<uint4*>(h);
    } else {
        int i = idx - XCHUNKS;
        uint32_t w;
        asm volatile("ld.global.cs.b32 %0, [%1];" : "=r"(w) : "l"(wp + i));
        int o  = i >> 9;
        int wk = i & 511;
        int g  = wk >> 4;
        float s = scales[o * GROUPS + g];
        float b = biases[o * GROUPS + g];
        __half h[8];
#pragma unroll
        for (int j = 0; j < 8; j++) {
            float q = (float)((w >> (4 * j)) & 15u);
            h[j] = __float2half(fmaf(s, q, b));
        }
        *reinterpret_cast<uint4*>(wh + (size_t)i * 8) = *reinterpret_cast<uint4*>(h);
    }
}

// ---------------- kernel 2: pipelined mma.sync fp16 GEMM ----------------
// CTA 128x128x64, 4 warps 2x2, warp tile 64x64, 2 CTAs/SM.
// R15 schedule (iteration-top copy issue -> ~1.75-iteration copy slack;
// all stage reads pre-barrier; post-barrier = register-only MMA backlog),
// mainloop unrolled x4: stage bases and k0 wraps become compile-time
// constants, removing glue ALU from the issue stream. asm volatile order
// pins the proven schedule.
__global__ void __launch_bounds__(128, 2)
gemm_f16_kernel(const __half* __restrict__ Ag, const __half* __restrict__ Bg,
                const float* __restrict__ bias, float* __restrict__ out) {
    extern __shared__ char smem[];
    const uint32_t sbase = smem_u32(smem);

    const int tid = threadIdx.x;
    const int wid = tid >> 5;
    const int lid = tid & 31;

    // ---- supertiled tile decode ----
    int nt, mt;
    {
        const int per = MT * GROUP_N;          // 1024 tiles per full group
        int gi = blockIdx.x / per;
        int within = blockIdx.x % per;
        int gbase = gi * GROUP_N;
        int gw = NT - gbase; if (gw > GROUP_N) gw = GROUP_N;
        mt = within / gw;
        nt = gbase + within % gw;
    }

    // de-phase co-resident CTAs (wave-1 pairs are bid and bid+148)
    const int koff = ((blockIdx.x / 148) & 1) * (NITER / 2);

    const int warp_m = wid >> 1;
    const int warp_n = wid & 1;
    const int m_base = warp_m * 64;
    const int n_base = warp_n * 64;

    const __half* Agb = Ag + (size_t)mt * BLOCK_M * IN_F;
    const __half* Bgb = Bg + (size_t)nt * BLOCK_N * IN_F;

    // ---- ldmatrix per-thread precompute ----
    const int r  = lid & 7;
    const int gq = lid >> 3;
    const uint32_t xorv = r * 16;
    const uint32_t aRowOff = (uint32_t)(m_base + r + 8 * (gq & 1)) * 128;
    const uint32_t aKExtra = 16 * (gq >> 1);
    const uint32_t bRowOff = (uint32_t)(n_base + r) * 128 + (uint32_t)(gq >> 1) * 1024;
    const uint32_t bKExtra = 16 * (gq & 1);

    float c[4][8][4];
#pragma unroll
    for (int mf = 0; mf < 4; mf++)
#pragma unroll
        for (int nf = 0; nf < 8; nf++)
#pragma unroll
            for (int k = 0; k < 4; k++) c[mf][nf][k] = 0.f;

    // ---- async load: logical iter it -> physical chunk (it+koff)&63 ----
    auto load_stage = [&](int it, int stage) {
        const uint32_t sA = sbase + stage * STAGE_BYTES;
        const uint32_t sB = sA + A_BYTES;
        const int k0 = ((it + koff) & (NITER - 1)) * BLOCK_K;
#pragma unroll
        for (int k = 0; k < 8; k++) {           // A
            int i = tid + 128 * k;
            int row = i >> 3, cc = i & 7;
            const __half* gp = Agb + (size_t)row * IN_F + k0 + cc * 8;
            uint32_t sp = sA + row * 128 + ((cc * 16) ^ ((row & 7) * 16));
            CP_ASYNC_CG(sp, gp);
        }
#pragma unroll
        for (int k = 0; k < 8; k++) {           // B
            int i = tid + 128 * k;
            int row = i >> 3, cc = i & 7;
            const __half* gp = Bgb + (size_t)row * IN_F + k0 + cc * 8;
            uint32_t sp = sB + row * 128 + ((cc * 16) ^ ((row & 7) * 16));
            CP_ASYNC_CG(sp, gp);
        }
    };

    uint32_t a[2][4][4], b[2][4][4];
    auto ldfrags = [&](uint32_t sA, int buf, int ks) {
        const uint32_t sB = sA + A_BYTES;
        const uint32_t ak = (uint32_t)(ks * 32);
#pragma unroll
        for (int mf = 0; mf < 4; mf++)
            LDSM_X4(a[buf][mf], sA + aRowOff + mf * 2048 + ((ak + aKExtra) ^ xorv));
#pragma unroll
        for (int jb = 0; jb < 4; jb++)
            LDSM_X4(b[buf][jb], sB + bRowOff + jb * 2048 + ((ak + bKExtra) ^ xorv));
    };
    auto mmastep = [&](int buf) {
#pragma unroll
        for (int mf = 0; mf < 4; mf++)
#pragma unroll
            for (int nf = 0; nf < 8; nf++)
                MMA16816(c[mf][nf], a[buf][mf], &b[buf][nf >> 1][(nf & 1) * 2]);
    };

    // prologue: fill stages 0,1; make stage 0 readable; preload ks0 frags
    load_stage(0, 0); CP_COMMIT();
    load_stage(1, 1); CP_COMMIT();
    CP_WAIT1();            // stage 0 ready (group 1 may be in flight)
    __syncthreads();
    ldfrags(sbase, 0, 0);

#pragma unroll 4
    for (int it = 0; it < NITER; it++) {
        const uint32_t sA  = sbase + (it % STAGES) * STAGE_BYTES;
        const uint32_t sAn = sbase + ((it + 1) % STAGES) * STAGE_BYTES;

        // iteration-top issue of stage it+2 copies (destination slot's last
        // reads completed before barrier it-1); ~1.75-iteration copy slack.
        // Previous iteration's tensor backlog covers the cp.async issues.
        if (it + 2 < NITER) load_stage(it + 2, (it + 2) % STAGES);
        CP_COMMIT();           // unconditional: uniform group accounting

        ldfrags(sA, 1, 1);     // stage it readable since previous barrier
        mmastep(0);            // ks=0
        ldfrags(sA, 0, 2);
        mmastep(1);            // ks=1
        ldfrags(sA, 1, 3);     // last read of stage it (pre-barrier)

        CP_WAIT1();            // drain group it+1 -> stage it+1 data landed
        __syncthreads();       // visibility + stage-reuse ordering

        mmastep(0);            // ks=2 — register-only, absorbs barrier release
        mmastep(1);            // ks=3 — register-only, queues tensor backlog
        if (it + 1 < NITER) ldfrags(sAn, 0, 0);   // next iter ks0 under backlog
    }

    // ---- epilogue: add bias, streaming fp32 stores ----
    const int m_lo = lid >> 2;
    const int n_lo = (lid & 3) * 2;
    const int n_col0 = nt * BLOCK_N + n_base + n_lo;

    float2 bb[8];
#pragma unroll
    for (int nf = 0; nf < 8; nf++) {
        bb[nf].x = __ldg(bias + n_col0 + nf * 8);
        bb[nf].y = __ldg(bias + n_col0 + nf * 8 + 1);
    }

#pragma unroll
    for (int mf = 0; mf < 4; mf++) {
        size_t m0 = (size_t)mt * BLOCK_M + m_base + mf * 16 + m_lo;
#pragma unroll
        for (int nf = 0; nf < 8; nf++) {
            float v0x = c[mf][nf][0] + bb[nf].x;
            float v0y = c[mf][nf][1] + bb[nf].y;
            float v1x = c[mf][nf][2] + bb[nf].x;
            float v1y = c[mf][nf][3] + bb[nf].y;
            STG_CS_F32X2(out + m0 * OUT_F + n_col0 + nf * 8, v0x, v0y);
            STG_CS_F32X2(out + (m0 + 8) * OUT_F + n_col0 + nf * 8, v1x, v1y);
        }
    }
}

// ---------------- host ----------------
extern "C" void kernel_launch(void* const* d_in, const int* in_sizes, int n_in,
                              void* d_out, int out_size) {
    const float* x      = (const float*)d_in[0];
    const int*   wp     = (const int*)d_in[1];
    const float* scales = (const float*)d_in[2];
    const float* biases = (const float*)d_in[3];
    const float* bias   = (const float*)d_in[4];
    float* out = (float*)d_out;

    __half* xh = nullptr;
    __half* wh = nullptr;
    cudaGetSymbolAddress((void**)&xh, g_xh);
    cudaGetSymbolAddress((void**)&wh, g_wh);

    prep_kernel<<<(XCHUNKS + WWORDS) / 256, 256>>>(
        (const float4*)x, (uint4*)xh, wp, scales, biases, wh);

    cudaFuncSetAttribute(gemm_f16_kernel, cudaFuncAttributeMaxDynamicSharedMemorySize, SMEM_BYTES);
    gemm_f16_kernel<<<MT * NT, 128, SMEM_BYTES>>>(xh, wh, bias, out);
}

// round 17
// speedup vs baseline: 1.0066x; 1.0066x over previous
#include <cuda_runtime.h>
#include <cuda_fp16.h>
#include <cstdint>

// ---------------- problem dims ----------------
#define IN_F   4096
#define OUT_F  11008
#define M_TOT  8192
#define GROUPS 32
#define PACKED 512

// ---------------- GEMM tiling ----------------
#define BLOCK_M 128
#define BLOCK_N 128
#define BLOCK_K 64            // 64 halves = 128B rows
#define STAGES  3
#define NITER   (IN_F / BLOCK_K)   // 64
#define NT      (OUT_F / BLOCK_N)  // 86
#define MT      (M_TOT / BLOCK_M)  // 64
#define GROUP_N 16                 // nt-supertile width for L2 locality

#define A_BYTES (BLOCK_M * 128)            // 16384
#define B_BYTES (BLOCK_N * 128)            // 16384
#define STAGE_BYTES (A_BYTES + B_BYTES)    // 32768
#define BIAS_SMEM (STAGES * STAGE_BYTES)   // bias vector after the stages
#define SMEM_BYTES (BIAS_SMEM + BLOCK_N * 4)  // 98816 (2 CTAs/SM -> 197632)

// prep work split
#define XCHUNKS (M_TOT * IN_F / 8)
#define WWORDS  (OUT_F * PACKED)

// ---------------- scratch (device globals: allocation-free) ----------------
__device__ __align__(1024) __half g_xh[(size_t)M_TOT * IN_F];
__device__ __align__(1024) __half g_wh[(size_t)OUT_F * IN_F];

// ---------------- PTX helpers ----------------
__device__ __forceinline__ uint32_t smem_u32(const void* p) {
    uint32_t a;
    asm("{ .reg .u64 t; cvta.to.shared.u64 t, %1; cvt.u32.u64 %0, t; }" : "=r"(a) : "l"(p));
    return a;
}

#define CP_ASYNC_CG(smem, gptr) \
    asm volatile("cp.async.cg.shared.global [%0], [%1], 16;" :: "r"(smem), "l"(gptr) : "memory")
#define CP_COMMIT() asm volatile("cp.async.commit_group;" ::: "memory")
#define CP_WAIT1()  asm volatile("cp.async.wait_group 1;" ::: "memory")

#define LDSM_X4(R, addr) \
    asm volatile("ldmatrix.sync.aligned.m8n8.x4.shared.b16 {%0,%1,%2,%3}, [%4];" \
                 : "=r"((R)[0]), "=r"((R)[1]), "=r"((R)[2]), "=r"((R)[3]) : "r"(addr))

#define MMA16816(C, A, B) \
    asm volatile("mma.sync.aligned.m16n8k16.row.col.f32.f16.f16.f32 " \
                 "{%0,%1,%2,%3}, {%4,%5,%6,%7}, {%8,%9}, {%0,%1,%2,%3};" \
                 : "+f"((C)[0]), "+f"((C)[1]), "+f"((C)[2]), "+f"((C)[3]) \
                 : "r"((A)[0]), "r"((A)[1]), "r"((A)[2]), "r"((A)[3]), \
                   "r"((B)[0]), "r"((B)[1]))

// streaming (evict-first) fp32x2 store: output is never re-read.
#define STG_CS_F32X2(ptr, vx, vy) \
    asm volatile("st.global.cs.v2.f32 [%0], {%1, %2};" :: "l"(ptr), "f"(vx), "f"(vy) : "memory")

// streaming 16B load (read-once inputs in prep)
__device__ __forceinline__ uint4 ldcs_u4(const uint4* p) {
    uint4 v;
    asm volatile("ld.global.cs.v4.b32 {%0,%1,%2,%3}, [%4];"
                 : "=r"(v.x), "=r"(v.y), "=r"(v.z), "=r"(v.w) : "l"(p));
    return v;
}

// ---------------- kernel 1: fused prep (x fp32->fp16, W int4->fp16) ----------------
__global__ void prep_kernel(const float4* __restrict__ x, uint4* __restrict__ xh,
                            const int* __restrict__ wp, const float* __restrict__ scales,
                            const float* __restrict__ biases, __half* __restrict__ wh) {
    int idx = blockIdx.x * blockDim.x + threadIdx.x;
    if (idx < XCHUNKS) {
        uint4 ua = ldcs_u4((const uint4*)(x + 2 * idx));
        uint4 ub = ldcs_u4((const uint4*)(x + 2 * idx + 1));
        float4 a = *reinterpret_cast<float4*>(&ua);
        float4 b = *reinterpret_cast<float4*>(&ub);
        __half h[8];
        h[0] = __float2half(a.x); h[1] = __float2half(a.y);
        h[2] = __float2half(a.z); h[3] = __float2half(a.w);
        h[4] = __float2half(b.x); h[5] = __float2half(b.y);
        h[6] = __float2half(b.z); h[7] = __float2half(b.w);
        xh[idx] = *reinterpret_cast<uint4*>(h);
    } else {
        int i = idx - XCHUNKS;
        uint32_t w;
        asm volatile("ld.global.cs.b32 %0, [%1];" : "=r"(w) : "l"(wp + i));
        int o  = i >> 9;
        int wk = i & 511;
        int g  = wk >> 4;
        float s = scales[o * GROUPS + g];
        float b = biases[o * GROUPS + g];
        __half h[8];
#pragma unroll
        for (int j = 0; j < 8; j++) {
            float q = (float)((w >> (4 * j)) & 15u);
            h[j] = __float2half(fmaf(s, q, b));
        }
        *reinterpret_cast<uint4*>(wh + (size_t)i * 8) = *reinterpret_cast<uint4*>(h);
    }
}

// ---------------- kernel 2: pipelined mma.sync fp16 GEMM ----------------
// CTA 128x128x64, 4 warps 2x2, warp tile 64x64, 2 CTAs/SM.
// Best-measured schedule (R15): iteration-top copy issue (~1.75-iteration
// copy slack), all stage reads pre-barrier, post-barrier = register-only
// MMA backlog absorbing barrier release, tail ks0 prefetch after the bursts.
// New: bias staged into SMEM during the prologue so the epilogue reads it
// via 29-cyc LDS instead of ~234-cyc L2 on the critical store path.
__global__ void __launch_bounds__(128, 2)
gemm_f16_kernel(const __half* __restrict__ Ag, const __half* __restrict__ Bg,
                const float* __restrict__ bias, float* __restrict__ out) {
    extern __shared__ char smem[];
    const uint32_t sbase = smem_u32(smem);
    const uint32_t sbias = sbase + BIAS_SMEM;

    const int tid = threadIdx.x;
    const int wid = tid >> 5;
    const int lid = tid & 31;

    // ---- supertiled tile decode ----
    int nt, mt;
    {
        const int per = MT * GROUP_N;          // 1024 tiles per full group
        int gi = blockIdx.x / per;
        int within = blockIdx.x % per;
        int gbase = gi * GROUP_N;
        int gw = NT - gbase; if (gw > GROUP_N) gw = GROUP_N;
        mt = within / gw;
        nt = gbase + within % gw;
    }

    // de-phase co-resident CTAs (wave-1 pairs are bid and bid+148)
    const int koff = ((blockIdx.x / 148) & 1) * (NITER / 2);

    const int warp_m = wid >> 1;
    const int warp_n = wid & 1;
    const int m_base = warp_m * 64;
    const int n_base = warp_n * 64;

    const __half* Agb = Ag + (size_t)mt * BLOCK_M * IN_F;
    const __half* Bgb = Bg + (size_t)nt * BLOCK_N * IN_F;

    // ---- ldmatrix per-thread precompute ----
    const int r  = lid & 7;
    const int gq = lid >> 3;
    const uint32_t xorv = r * 16;
    const uint32_t aRowOff = (uint32_t)(m_base + r + 8 * (gq & 1)) * 128;
    const uint32_t aKExtra = 16 * (gq >> 1);
    const uint32_t bRowOff = (uint32_t)(n_base + r) * 128 + (uint32_t)(gq >> 1) * 1024;
    const uint32_t bKExtra = 16 * (gq & 1);

    float c[4][8][4];
#pragma unroll
    for (int mf = 0; mf < 4; mf++)
#pragma unroll
        for (int nf = 0; nf < 8; nf++)
#pragma unroll
            for (int k = 0; k < 4; k++) c[mf][nf][k] = 0.f;

    // ---- async load: logical iter it -> physical chunk (it+koff)&63 ----
    auto load_stage = [&](int it, int stage) {
        const uint32_t sA = sbase + stage * STAGE_BYTES;
        const uint32_t sB = sA + A_BYTES;
        const int k0 = ((it + koff) & (NITER - 1)) * BLOCK_K;
#pragma unroll
        for (int k = 0; k < 8; k++) {           // A
            int i = tid + 128 * k;
            int row = i >> 3, cc = i & 7;
            const __half* gp = Agb + (size_t)row * IN_F + k0 + cc * 8;
            uint32_t sp = sA + row * 128 + ((cc * 16) ^ ((row & 7) * 16));
            CP_ASYNC_CG(sp, gp);
        }
#pragma unroll
        for (int k = 0; k < 8; k++) {           // B
            int i = tid + 128 * k;
            int row = i >> 3, cc = i & 7;
            const __half* gp = Bgb + (size_t)row * IN_F + k0 + cc * 8;
            uint32_t sp = sB + row * 128 + ((cc * 16) ^ ((row & 7) * 16));
            CP_ASYNC_CG(sp, gp);
        }
    };

    uint32_t a[2][4][4], b[2][4][4];
    auto ldfrags = [&](uint32_t sA, int buf, int ks) {
        const uint32_t sB = sA + A_BYTES;
        const uint32_t ak = (uint32_t)(ks * 32);
#pragma unroll
        for (int mf = 0; mf < 4; mf++)
            LDSM_X4(a[buf][mf], sA + aRowOff + mf * 2048 + ((ak + aKExtra) ^ xorv));
#pragma unroll
        for (int jb = 0; jb < 4; jb++)
            LDSM_X4(b[buf][jb], sB + bRowOff + jb * 2048 + ((ak + bKExtra) ^ xorv));
    };
    auto mmastep = [&](int buf) {
#pragma unroll
        for (int mf = 0; mf < 4; mf++)
#pragma unroll
            for (int nf = 0; nf < 8; nf++)
                MMA16816(c[mf][nf], a[buf][mf], &b[buf][nf >> 1][(nf & 1) * 2]);
    };

    // prologue: fill stages 0,1; stage bias into smem (latency hidden under
    // the cp.async fill; ordered for all threads by the prologue barrier)
    load_stage(0, 0); CP_COMMIT();
    load_stage(1, 1); CP_COMMIT();
    {
        float bv = __ldg(bias + nt * BLOCK_N + tid);   // tid < 128 = BLOCK_N
        asm volatile("st.shared.f32 [%0], %1;" :: "r"(sbias + tid * 4), "f"(bv) : "memory");
    }
    CP_WAIT1();            // stage 0 ready (group 1 may be in flight)
    __syncthreads();
    ldfrags(sbase, 0, 0);

#pragma unroll 1
    for (int it = 0; it < NITER; it++) {
        const uint32_t sA  = sbase + (it % STAGES) * STAGE_BYTES;
        const uint32_t sAn = sbase + ((it + 1) % STAGES) * STAGE_BYTES;

        // iteration-top issue of stage it+2 copies (destination slot's last
        // reads completed before barrier it-1); ~1.75-iteration copy slack.
        // Previous iteration's tensor backlog covers the cp.async issues.
        if (it + 2 < NITER) load_stage(it + 2, (it + 2) % STAGES);
        CP_COMMIT();           // unconditional: uniform group accounting

        ldfrags(sA, 1, 1);     // stage it readable since previous barrier
        mmastep(0);            // ks=0
        ldfrags(sA, 0, 2);
        mmastep(1);            // ks=1
        ldfrags(sA, 1, 3);     // last read of stage it (pre-barrier)

        CP_WAIT1();            // drain group it+1 -> stage it+1 data landed
        __syncthreads();       // visibility + stage-reuse ordering

        mmastep(0);            // ks=2 — register-only, absorbs barrier release
        mmastep(1);            // ks=3 — register-only, queues tensor backlog
        if (it + 1 < NITER) ldfrags(sAn, 0, 0);   // next iter ks0 under backlog
    }

    // ---- epilogue: add bias (from smem), streaming fp32 stores ----
    const int m_lo = lid >> 2;
    const int n_lo = (lid & 3) * 2;
    const int n_col0 = nt * BLOCK_N + n_base + n_lo;
    const uint32_t sb0 = sbias + (uint32_t)(n_base + n_lo) * 4;

#pragma unroll
    for (int mf = 0; mf < 4; mf++) {
        size_t m0 = (size_t)mt * BLOCK_M + m_base + mf * 16 + m_lo;
#pragma unroll
        for (int nf = 0; nf < 8; nf++) {
            float bx, by;
            asm volatile("ld.shared.v2.f32 {%0, %1}, [%2];"
                         : "=f"(bx), "=f"(by) : "r"(sb0 + nf * 32));
            float v0x = c[mf][nf][0] + bx;
            float v0y = c[mf][nf][1] + by;
            float v1x = c[mf][nf][2] + bx;
            float v1y = c[mf][nf][3] + by;
            STG_CS_F32X2(out + m0 * OUT_F + n_col0 + nf * 8, v0x, v0y);
            STG_CS_F32X2(out + (m0 + 8) * OUT_F + n_col0 + nf * 8, v1x, v1y);
        }
    }
}

// ---------------- host ----------------
extern "C" void kernel_launch(void* const* d_in, const int* in_sizes, int n_in,
                              void* d_out, int out_size) {
    const float* x      = (const float*)d_in[0];
    const int*   wp     = (const int*)d_in[1];
    const float* scales = (const float*)d_in[2];
    const float* biases = (const float*)d_in[3];
    const float* bias   = (const float*)d_in[4];
    float* out = (float*)d_out;

    __half* xh = nullptr;
    __half* wh = nullptr;
    cudaGetSymbolAddress((void**)&xh, g_xh);
    cudaGetSymbolAddress((void**)&wh, g_wh);

    prep_kernel<<<(XCHUNKS + WWORDS) / 256, 256>>>(
        (const float4*)x, (uint4*)xh, wp, scales, biases, wh);

    cudaFuncSetAttribute(gemm_f16_kernel, cudaFuncAttributeMaxDynamicSharedMemorySize, SMEM_BYTES);
    gemm_f16_kernel<<<MT * NT, 128, SMEM_BYTES>>>(xh, wh, bias, out);
}